// round 10
// baseline (speedup 1.0000x reference)
#include <cuda_runtime.h>
#include <math.h>

#define N_NODES 20000
#define N_EDGES 100000

typedef unsigned long long ull;

// scratch (static __device__ per harness rules)
// g_node layout per node (512 floats): [s(128) | v0(128) | v1(128) | v2(128)]
static __device__ float g_node[N_NODES * 512];
static __device__ float g_h[N_EDGES * 64];

#define SILU_NORM 1.6790390826f

__device__ __forceinline__ float act(float x) {
    return SILU_NORM * x / (1.0f + __expf(-x));
}

__device__ __forceinline__ ull pk2(float lo, float hi) {
    ull r; asm("mov.b64 %0, {%1,%2};" : "=l"(r) : "f"(lo), "f"(hi)); return r;
}
__device__ __forceinline__ void fma2(ull& d, ull a, ull b) {
    asm("fma.rn.f32x2 %0, %1, %2, %0;" : "+l"(d) : "l"(a), "l"(b));
}
__device__ __forceinline__ ull mul2(ull a, ull b) {
    ull r; asm("mul.rn.f32x2 %0, %1, %2;" : "=l"(r) : "l"(a), "l"(b)); return r;
}
__device__ __forceinline__ float rsum(ull v) {
    float lo, hi; asm("mov.b64 {%0,%1}, %2;" : "=f"(lo), "=f"(hi) : "l"(v));
    return lo + hi;
}

// ---------------------------------------------------------------------------
// Kernel 1: node up-projection (SoA output), f32x2, 2 nodes per warp.
// 256 threads / 8 warps: warp w handles nodes base+w and base+w+8 (16/iter).
// Weight LDS is shared across the 2 nodes -> halves smem traffic per FMA.
// smem fl: sWsP 16384 | sWvP 16384 | snf 8192 = 40960 fl (160 KB)
// N_NODES % 16 == 0 -> no bounds checks in compute.
// ---------------------------------------------------------------------------
__global__ void __launch_bounds__(256) node_kernel(
    const float* __restrict__ nf,
    const float* __restrict__ Wus,
    const float* __restrict__ Wuv)
{
    extern __shared__ float sm[];
    ull* sWsP = (ull*)sm;             // 8192 ull
    ull* sWvP = (ull*)(sm + 16384);   // 8192 ull
    float* snf = sm + 32768;          // 16 nodes * 512
    int t = threadIdx.x;

    // stage pair-interleaved weights: [u2*128 + c] = {W[2u2][c], W[2u2+1][c]}
    for (int i = t; i < 8192; i += 256) {
        int u2 = i >> 7, c = i & 127;
        sWsP[i] = pk2(Wus[(2 * u2) * 128 + c], Wus[(2 * u2 + 1) * 128 + c]);
        sWvP[i] = pk2(Wuv[(2 * u2) * 128 + c], Wuv[(2 * u2 + 1) * 128 + c]);
    }
    __syncthreads();

    int warp = t >> 5, cg = t & 31;
    const float inv = 0.08838834764831845f; // 1/sqrt(128)

    for (int base = blockIdx.x * 16; base < N_NODES; base += gridDim.x * 16) {
        // stage 16 node rows, de-interleaving v: snf[nd][128 + 128*i + u]
        for (int i = t; i < 8192; i += 256) {
            int nd = i >> 9, ch = i & 511;
            float v = nf[(size_t)(base + nd) * 512 + ch];
            int pos;
            if (ch < 128) pos = ch;
            else { int j = ch - 128; pos = 128 + (j % 3) * 128 + j / 3; }
            snf[nd * 512 + pos] = v;
        }
        __syncthreads();

        const float* rowA = snf + warp * 512;
        const float* rowB = snf + (warp + 8) * 512;
        const ull* As = (const ull*)rowA;
        const ull* A0 = (const ull*)(rowA + 128);
        const ull* A1 = (const ull*)(rowA + 256);
        const ull* A2 = (const ull*)(rowA + 384);
        const ull* Bs = (const ull*)rowB;
        const ull* B0 = (const ull*)(rowB + 128);
        const ull* B1 = (const ull*)(rowB + 256);
        const ull* B2 = (const ull*)(rowB + 384);

        ull aA[16], aB[16];
        #pragma unroll
        for (int i = 0; i < 16; ++i) { aA[i] = 0; aB[i] = 0; }

        #pragma unroll 4
        for (int u2 = 0; u2 < 64; ++u2) {
            ulonglong2 bsA = *(const ulonglong2*)(sWsP + u2 * 128 + 4 * cg);
            ulonglong2 bsB = *(const ulonglong2*)(sWsP + u2 * 128 + 4 * cg + 2);
            ulonglong2 bvA = *(const ulonglong2*)(sWvP + u2 * 128 + 4 * cg);
            ulonglong2 bvB = *(const ulonglong2*)(sWvP + u2 * 128 + 4 * cg + 2);
            ull xs, x0, x1, x2;
            // node A
            xs = As[u2]; x0 = A0[u2]; x1 = A1[u2]; x2 = A2[u2];
            fma2(aA[0],  xs, bsA.x); fma2(aA[1],  xs, bsA.y);
            fma2(aA[2],  xs, bsB.x); fma2(aA[3],  xs, bsB.y);
            fma2(aA[4],  x0, bvA.x); fma2(aA[5],  x0, bvA.y);
            fma2(aA[6],  x0, bvB.x); fma2(aA[7],  x0, bvB.y);
            fma2(aA[8],  x1, bvA.x); fma2(aA[9],  x1, bvA.y);
            fma2(aA[10], x1, bvB.x); fma2(aA[11], x1, bvB.y);
            fma2(aA[12], x2, bvA.x); fma2(aA[13], x2, bvA.y);
            fma2(aA[14], x2, bvB.x); fma2(aA[15], x2, bvB.y);
            // node B (reuses the same staged weights)
            xs = Bs[u2]; x0 = B0[u2]; x1 = B1[u2]; x2 = B2[u2];
            fma2(aB[0],  xs, bsA.x); fma2(aB[1],  xs, bsA.y);
            fma2(aB[2],  xs, bsB.x); fma2(aB[3],  xs, bsB.y);
            fma2(aB[4],  x0, bvA.x); fma2(aB[5],  x0, bvA.y);
            fma2(aB[6],  x0, bvB.x); fma2(aB[7],  x0, bvB.y);
            fma2(aB[8],  x1, bvA.x); fma2(aB[9],  x1, bvA.y);
            fma2(aB[10], x1, bvB.x); fma2(aB[11], x1, bvB.y);
            fma2(aB[12], x2, bvA.x); fma2(aB[13], x2, bvA.y);
            fma2(aB[14], x2, bvB.x); fma2(aB[15], x2, bvB.y);
        }

        float* oA = g_node + (size_t)(base + warp) * 512;
        float* oB = g_node + (size_t)(base + warp + 8) * 512;
        #pragma unroll
        for (int s = 0; s < 4; ++s) {
            float4 r;
            r.x = rsum(aA[s*4+0]) * inv; r.y = rsum(aA[s*4+1]) * inv;
            r.z = rsum(aA[s*4+2]) * inv; r.w = rsum(aA[s*4+3]) * inv;
            ((float4*)(oA + 128 * s))[cg] = r;
            r.x = rsum(aB[s*4+0]) * inv; r.y = rsum(aB[s*4+1]) * inv;
            r.z = rsum(aB[s*4+2]) * inv; r.w = rsum(aB[s*4+3]) * inv;
            ((float4*)(oB + 128 * s))[cg] = r;
        }
        __syncthreads();
    }
}

// ---------------------------------------------------------------------------
// Kernel 2: edge MLP layers 0..2 -> g_h.  128 edges/CTA, 128 threads. (R3 proven)
// ---------------------------------------------------------------------------
__global__ void __launch_bounds__(128) mlp_kernel(
    const float* __restrict__ ef,
    const float* __restrict__ w0,
    const float* __restrict__ w1,
    const float* __restrict__ w2)
{
    extern __shared__ float sm[];
    float* sw0 = sm;              // 512
    float* sw1 = sw0 + 512;       // 4096
    float* sw2 = sw1 + 4096;      // 4096
    float* sef = sw2 + 4096;      // 1024
    float* hA  = sef + 1024;      // 128*65
    float* hB  = hA + 128 * 65;   // 128*65

    int t = threadIdx.x;
    const float is8 = 0.35355339059327373f; // 1/sqrt(8)
    for (int i = t; i < 512; i += 128) sw0[i] = w0[i] * is8;
    for (int i = t; i < 4096; i += 128) { sw1[i] = w1[i] * 0.125f; sw2[i] = w2[i] * 0.125f; }
    int ebase = blockIdx.x * 128;
    int nvalid = N_EDGES - ebase; if (nvalid > 128) nvalid = 128;
    for (int i = t; i < 1024; i += 128)
        sef[i] = (i < nvalid * 8) ? ef[ebase * 8 + i] : 0.f;
    __syncthreads();

    int es = t & 31;
    int dg = t >> 5;
    float acc[4][16];

    // layer 0
    #pragma unroll
    for (int k = 0; k < 4; ++k)
        #pragma unroll
        for (int d = 0; d < 16; ++d) acc[k][d] = 0.f;
    #pragma unroll
    for (int u = 0; u < 8; ++u) {
        float x0 = sef[(es      ) * 8 + u];
        float x1 = sef[(es + 32) * 8 + u];
        float x2 = sef[(es + 64) * 8 + u];
        float x3 = sef[(es + 96) * 8 + u];
        #pragma unroll
        for (int d = 0; d < 16; ++d) {
            float w = sw0[u * 64 + dg * 16 + d];
            acc[0][d] += x0 * w; acc[1][d] += x1 * w; acc[2][d] += x2 * w; acc[3][d] += x3 * w;
        }
    }
    #pragma unroll
    for (int k = 0; k < 4; ++k)
        #pragma unroll
        for (int d = 0; d < 16; ++d)
            hA[(es + 32 * k) * 65 + dg * 16 + d] = act(acc[k][d]);
    __syncthreads();

    // layer 1
    #pragma unroll
    for (int k = 0; k < 4; ++k)
        #pragma unroll
        for (int d = 0; d < 16; ++d) acc[k][d] = 0.f;
    #pragma unroll 8
    for (int u = 0; u < 64; ++u) {
        float x0 = hA[(es      ) * 65 + u];
        float x1 = hA[(es + 32) * 65 + u];
        float x2 = hA[(es + 64) * 65 + u];
        float x3 = hA[(es + 96) * 65 + u];
        #pragma unroll
        for (int d = 0; d < 16; ++d) {
            float w = sw1[u * 64 + dg * 16 + d];
            acc[0][d] += x0 * w; acc[1][d] += x1 * w; acc[2][d] += x2 * w; acc[3][d] += x3 * w;
        }
    }
    #pragma unroll
    for (int k = 0; k < 4; ++k)
        #pragma unroll
        for (int d = 0; d < 16; ++d)
            hB[(es + 32 * k) * 65 + dg * 16 + d] = act(acc[k][d]);
    __syncthreads();

    // layer 2 -> g_h
    #pragma unroll
    for (int k = 0; k < 4; ++k)
        #pragma unroll
        for (int d = 0; d < 16; ++d) acc[k][d] = 0.f;
    #pragma unroll 8
    for (int u = 0; u < 64; ++u) {
        float x0 = hB[(es      ) * 65 + u];
        float x1 = hB[(es + 32) * 65 + u];
        float x2 = hB[(es + 64) * 65 + u];
        float x3 = hB[(es + 96) * 65 + u];
        #pragma unroll
        for (int d = 0; d < 16; ++d) {
            float w = sw2[u * 64 + dg * 16 + d];
            acc[0][d] += x0 * w; acc[1][d] += x1 * w; acc[2][d] += x2 * w; acc[3][d] += x3 * w;
        }
    }
    #pragma unroll
    for (int k = 0; k < 4; ++k) {
        int e = ebase + es + 32 * k;
        if (e < N_EDGES) {
            #pragma unroll
            for (int d = 0; d < 16; ++d)
                g_h[(size_t)e * 64 + dg * 16 + d] = act(acc[k][d]);
        }
    }
}

// ---------------------------------------------------------------------------
// Kernel 3: fused tpw + tensor product + output GEMMs, K-packed f32x2.
// 32 edges/CTA, 256 threads (warp w owns edges 4w..4w+3; lane cg owns cols 4cg..+3)
// out_v factorization: out_v[e,n,i] = sh1_i * (P@Wv_top)[e,n] + ((Q*vs_i)@Wv_bot)[e,n]
// ssv uses SoA node layout [s|v0|v1|v2].
// smem fl: ssv 16384 | sA 8192 | sP 4096 | sQ 4096 | sh 2048 | sWp 8192 | sea 128 | snd 32
// ---------------------------------------------------------------------------
// stage a 64-row x 128-col chunk of row-major src, pair-interleaved over K:
// dst[u2*128+c] = {src[row0+2u2][col0+c], src[row0+2u2+1][col0+c]}, u2<32
__device__ __forceinline__ void stageP(ull* dst, const float* __restrict__ src,
                                       int row0, int rowStride, int col0, int t) {
    #pragma unroll
    for (int j = 0; j < 16; ++j) {
        int i = t + 256 * j;                 // < 4096
        int u2 = i >> 7, c = i & 127;
        const float* p = src + (size_t)(row0 + 2 * u2) * rowStride + col0 + c;
        dst[i] = pk2(p[0], p[rowStride]);
    }
}

__global__ void __launch_bounds__(256) edge_kernel(
    const float* __restrict__ ea,     // edge_attrs (E,4)
    const int*   __restrict__ eidx,   // edge_index (2,E): sender first
    const float* __restrict__ w3,     // (64,512)
    const float* __restrict__ Wos,    // (256,128)
    const float* __restrict__ Wov,    // (256,128)
    float* __restrict__ out)
{
    extern __shared__ float sm[];
    float* ssv = sm;                  // 32*512 = 16384 (gathered, SoA)
    float* sA  = ssv + 16384;         // 32*256 = 8192
    float* sP  = sA + 8192;           // 32*128 = 4096
    float* sQ  = sP + 4096;           // 32*128 = 4096
    float* sh  = sQ + 4096;           // 32*64  = 2048
    ull*   sWp = (ull*)(sh + 2048);   // 4096 ull = 8192 fl
    float* sea = sh + 2048 + 8192;    // 128
    int*   snd = (int*)(sea + 128);   // 32

    const float C0 = 0.70710678118654752f / 128.0f;                       // sqrt(.5)/(8*16)
    const float C3 = 0.70710678118654752f / (128.0f * 1.7320508075688772f);

    int t = threadIdx.x;
    int warp = t >> 5;
    int cg = t & 31;
    int ebase = blockIdx.x * 32;
    int e0 = warp * 4;

    if (t < 32) snd[t] = eidx[ebase + t];
    if (t >= 128 && t < 256) sea[t - 128] = ea[ebase * 4 + (t - 128)];
    __syncthreads();

    { // gather node rows (32 x 512 floats, 8 threads/row, float4)
        int r = t >> 3, q = t & 7;
        const float4* src = (const float4*)g_node + (size_t)snd[r] * 128;
        float4* dst = (float4*)ssv + r * 128;
        #pragma unroll
        for (int j = 0; j < 16; ++j) dst[q + 8 * j] = src[q + 8 * j];
    }
    { // h tile (512 float4)
        const float4* src = (const float4*)g_h + (size_t)ebase * 16;
        float4* dst = (float4*)sh;
        dst[t] = src[t];
        dst[t + 256] = src[t + 256];
    }

    // ---- tpw chunks -> A / P / Q (coefficients folded), K=64 packed ----
    for (int c = 0; c < 4; ++c) {
        __syncthreads();   // also covers ssv/sh staging on first iteration
        stageP(sWp, w3, 0, 512, 128 * c, t);
        __syncthreads();

        ull acc[4][4];
        #pragma unroll
        for (int k = 0; k < 4; ++k) { acc[k][0]=0; acc[k][1]=0; acc[k][2]=0; acc[k][3]=0; }
        #pragma unroll 4
        for (int u2 = 0; u2 < 32; ++u2) {
            ulonglong2 bA = *(const ulonglong2*)(sWp + u2 * 128 + 4 * cg);
            ulonglong2 bB = *(const ulonglong2*)(sWp + u2 * 128 + 4 * cg + 2);
            #pragma unroll
            for (int k = 0; k < 4; ++k) {
                ull a = ((const ull*)(sh + (e0 + k) * 64))[u2];
                fma2(acc[k][0], a, bA.x); fma2(acc[k][1], a, bA.y);
                fma2(acc[k][2], a, bB.x); fma2(acc[k][3], a, bB.y);
            }
        }
        #pragma unroll
        for (int k = 0; k < 4; ++k) {
            int e = e0 + k;
            float r0 = rsum(acc[k][0]), r1 = rsum(acc[k][1]);
            float r2 = rsum(acc[k][2]), r3 = rsum(acc[k][3]);
            float s0 = sea[e * 4];
            if (c == 0) {
                float4 sv = ((const float4*)(ssv + e * 512))[cg];
                ((float4*)sA)[e * 64 + cg] = make_float4(
                    C0 * r0 * sv.x * s0, C0 * r1 * sv.y * s0,
                    C0 * r2 * sv.z * s0, C0 * r3 * sv.w * s0);
            } else if (c == 1) {
                float4 sv = ((const float4*)(ssv + e * 512))[cg];
                ((float4*)sP)[e * 32 + cg] = make_float4(
                    C0 * r0 * sv.x, C0 * r1 * sv.y, C0 * r2 * sv.z, C0 * r3 * sv.w);
            } else if (c == 2) {
                ((float4*)sQ)[e * 32 + cg] = make_float4(
                    C0 * r0 * s0, C0 * r1 * s0, C0 * r2 * s0, C0 * r3 * s0);
            } else {
                float s1 = sea[e * 4 + 1], s2 = sea[e * 4 + 2], s3 = sea[e * 4 + 3];
                float4 v0 = ((const float4*)(ssv + e * 512 + 128))[cg];
                float4 v1 = ((const float4*)(ssv + e * 512 + 256))[cg];
                float4 v2 = ((const float4*)(ssv + e * 512 + 384))[cg];
                ((float4*)sA)[e * 64 + 32 + cg] = make_float4(
                    C3 * r0 * (v0.x * s1 + v1.x * s2 + v2.x * s3),
                    C3 * r1 * (v0.y * s1 + v1.y * s2 + v2.y * s3),
                    C3 * r2 * (v0.z * s1 + v1.z * s2 + v2.z * s3),
                    C3 * r3 * (v0.w * s1 + v1.w * s2 + v2.w * s3));
            }
        }
    }

    // ---- out_s = A(32x256) @ Wos, K=256 packed, 4 kt stages ----
    {
        ull accs[4][4];
        #pragma unroll
        for (int k = 0; k < 4; ++k) { accs[k][0]=0; accs[k][1]=0; accs[k][2]=0; accs[k][3]=0; }
        for (int kt = 0; kt < 4; ++kt) {
            __syncthreads();
            stageP(sWp, Wos, 64 * kt, 128, 0, t);
            __syncthreads();
            #pragma unroll 4
            for (int u2 = 0; u2 < 32; ++u2) {
                ulonglong2 bA = *(const ulonglong2*)(sWp + u2 * 128 + 4 * cg);
                ulonglong2 bB = *(const ulonglong2*)(sWp + u2 * 128 + 4 * cg + 2);
                #pragma unroll
                for (int k = 0; k < 4; ++k) {
                    ull a = ((const ull*)(sA + (e0 + k) * 256))[kt * 32 + u2];
                    fma2(accs[k][0], a, bA.x); fma2(accs[k][1], a, bA.y);
                    fma2(accs[k][2], a, bB.x); fma2(accs[k][3], a, bB.y);
                }
            }
        }
        #pragma unroll
        for (int k = 0; k < 4; ++k) {
            size_t e = (size_t)(ebase + e0 + k);
            ((float4*)out)[e * 128 + cg] = make_float4(
                rsum(accs[k][0]), rsum(accs[k][1]), rsum(accs[k][2]), rsum(accs[k][3]));
        }
    }

    // ---- QV_i = (Q*vs_i) @ Wv_bot, per-i passes (acc capped at 16 ull) ----
    float qv[3][4][4];
    for (int i = 0; i < 3; ++i) {
        ull acc[4][4];
        #pragma unroll
        for (int k = 0; k < 4; ++k) { acc[k][0]=0; acc[k][1]=0; acc[k][2]=0; acc[k][3]=0; }
        for (int kt = 0; kt < 2; ++kt) {
            __syncthreads();
            stageP(sWp, Wov, 128 + 64 * kt, 128, 0, t);
            __syncthreads();
            #pragma unroll 2
            for (int u2 = 0; u2 < 32; ++u2) {
                ulonglong2 bA = *(const ulonglong2*)(sWp + u2 * 128 + 4 * cg);
                ulonglong2 bB = *(const ulonglong2*)(sWp + u2 * 128 + 4 * cg + 2);
                #pragma unroll
                for (int k = 0; k < 4; ++k) {
                    int e = e0 + k;
                    ull q = ((const ull*)(sQ + e * 128))[kt * 32 + u2];
                    ull v = ((const ull*)(ssv + e * 512 + 128 * (1 + i)))[kt * 32 + u2];
                    ull p = mul2(q, v);
                    fma2(acc[k][0], p, bA.x); fma2(acc[k][1], p, bA.y);
                    fma2(acc[k][2], p, bB.x); fma2(acc[k][3], p, bB.y);
                }
            }
        }
        #pragma unroll
        for (int k = 0; k < 4; ++k)
            #pragma unroll
            for (int j = 0; j < 4; ++j) qv[i][k][j] = rsum(acc[k][j]);
    }

    // ---- PV = P(32x128) @ Wv_top ----
    float pv[4][4];
    {
        ull accp[4][4];
        #pragma unroll
        for (int k = 0; k < 4; ++k) { accp[k][0]=0; accp[k][1]=0; accp[k][2]=0; accp[k][3]=0; }
        for (int kt = 0; kt < 2; ++kt) {
            __syncthreads();
            stageP(sWp, Wov, 64 * kt, 128, 0, t);
            __syncthreads();
            #pragma unroll 4
            for (int u2 = 0; u2 < 32; ++u2) {
                ulonglong2 bA = *(const ulonglong2*)(sWp + u2 * 128 + 4 * cg);
                ulonglong2 bB = *(const ulonglong2*)(sWp + u2 * 128 + 4 * cg + 2);
                #pragma unroll
                for (int k = 0; k < 4; ++k) {
                    ull a = ((const ull*)(sP + (e0 + k) * 128))[kt * 32 + u2];
                    fma2(accp[k][0], a, bA.x); fma2(accp[k][1], a, bA.y);
                    fma2(accp[k][2], a, bB.x); fma2(accp[k][3], a, bB.y);
                }
            }
        }
        #pragma unroll
        for (int k = 0; k < 4; ++k)
            #pragma unroll
            for (int j = 0; j < 4; ++j) pv[k][j] = rsum(accp[k][j]);
    }

    // ---- combine + restage out_v through smem for coalesced stores ----
    float* vbuf = sA;   // sA(8192)+sP(4096) contiguous = 12288 floats = 32*384
    __syncthreads();    // all reads of sA/sP complete before aliasing
    #pragma unroll
    for (int k = 0; k < 4; ++k) {
        int e = e0 + k;
        float s1 = sea[e * 4 + 1], s2 = sea[e * 4 + 2], s3 = sea[e * 4 + 3];
        #pragma unroll
        for (int j = 0; j < 4; ++j) {
            int n = cg * 4 + j;
            float p = pv[k][j];
            vbuf[e * 384 + n * 3 + 0] = s1 * p + qv[0][k][j];
            vbuf[e * 384 + n * 3 + 1] = s2 * p + qv[1][k][j];
            vbuf[e * 384 + n * 3 + 2] = s3 * p + qv[2][k][j];
        }
    }
    __syncthreads();
    float4* vb4 = (float4*)vbuf;
    #pragma unroll
    for (int j = 0; j < 12; ++j) {
        int idx = t + 256 * j;      // < 3072
        int e = idx / 96, rem = idx % 96;
        ((float4*)out)[(size_t)(ebase + e) * 128 + 32 + rem] = vb4[idx];
    }
}

// ---------------------------------------------------------------------------
extern "C" void kernel_launch(void* const* d_in, const int* in_sizes, int n_in,
                              void* d_out, int out_size) {
    const float* node_feats = (const float*)d_in[0];
    const float* edge_attrs = (const float*)d_in[1];
    const float* edge_feats = (const float*)d_in[2];
    const int*   edge_index = (const int*)d_in[3];
    const float* W_up_s  = (const float*)d_in[4];
    const float* W_up_v  = (const float*)d_in[5];
    const float* mlp_w0  = (const float*)d_in[6];
    const float* mlp_w1  = (const float*)d_in[7];
    const float* mlp_w2  = (const float*)d_in[8];
    const float* mlp_w3  = (const float*)d_in[9];
    const float* W_out_s = (const float*)d_in[10];
    const float* W_out_v = (const float*)d_in[11];
    float* out = (float*)d_out;

    size_t smem1 = (size_t)40960 * 4;   // 160 KB
    size_t smem2 = (size_t)26368 * 4;   // 103 KB
    size_t smem3 = (size_t)43200 * 4;   // 168.75 KB
    cudaFuncSetAttribute(node_kernel, cudaFuncAttributeMaxDynamicSharedMemorySize, (int)smem1);
    cudaFuncSetAttribute(mlp_kernel,  cudaFuncAttributeMaxDynamicSharedMemorySize, (int)smem2);
    cudaFuncSetAttribute(edge_kernel, cudaFuncAttributeMaxDynamicSharedMemorySize, (int)smem3);

    node_kernel<<<148, 256, smem1>>>(node_feats, W_up_s, W_up_v);
    mlp_kernel<<<(N_EDGES + 127) / 128, 128, smem2>>>(edge_feats, mlp_w0, mlp_w1, mlp_w2);
    edge_kernel<<<N_EDGES / 32, 256, smem3>>>(edge_attrs, edge_index, mlp_w3,
                                              W_out_s, W_out_v, out);
}

// round 11
// speedup vs baseline: 1.2020x; 1.2020x over previous
#include <cuda_runtime.h>
#include <math.h>

#define N_NODES 20000
#define N_EDGES 100000

typedef unsigned long long ull;

// scratch (static __device__ per harness rules)
// g_node layout per node (512 floats): [s(128) | v0(128) | v1(128) | v2(128)]
static __device__ float g_node[N_NODES * 512];
static __device__ float g_h[N_EDGES * 64];

#define SILU_NORM 1.6790390826f

__device__ __forceinline__ float act(float x) {
    return SILU_NORM * x / (1.0f + __expf(-x));
}

__device__ __forceinline__ ull pk2(float lo, float hi) {
    ull r; asm("mov.b64 %0, {%1,%2};" : "=l"(r) : "f"(lo), "f"(hi)); return r;
}
__device__ __forceinline__ void fma2(ull& d, ull a, ull b) {
    asm("fma.rn.f32x2 %0, %1, %2, %0;" : "+l"(d) : "l"(a), "l"(b));
}
__device__ __forceinline__ float rsum(ull v) {
    float lo, hi; asm("mov.b64 {%0,%1}, %2;" : "=f"(lo), "=f"(hi) : "l"(v));
    return lo + hi;
}

// ---------------------------------------------------------------------------
// Kernel 1: node up-projection (SoA output), f32x2, 2 nodes per warp.
// 256 threads / 8 warps: warp w handles nodes base+w and base+w+8 (16/iter).
// (measured 140us in R10)
// ---------------------------------------------------------------------------
__global__ void __launch_bounds__(256) node_kernel(
    const float* __restrict__ nf,
    const float* __restrict__ Wus,
    const float* __restrict__ Wuv)
{
    extern __shared__ float sm[];
    ull* sWsP = (ull*)sm;             // 8192 ull
    ull* sWvP = (ull*)(sm + 16384);   // 8192 ull
    float* snf = sm + 32768;          // 16 nodes * 512
    int t = threadIdx.x;

    for (int i = t; i < 8192; i += 256) {
        int u2 = i >> 7, c = i & 127;
        sWsP[i] = pk2(Wus[(2 * u2) * 128 + c], Wus[(2 * u2 + 1) * 128 + c]);
        sWvP[i] = pk2(Wuv[(2 * u2) * 128 + c], Wuv[(2 * u2 + 1) * 128 + c]);
    }
    __syncthreads();

    int warp = t >> 5, cg = t & 31;
    const float inv = 0.08838834764831845f; // 1/sqrt(128)

    for (int base = blockIdx.x * 16; base < N_NODES; base += gridDim.x * 16) {
        for (int i = t; i < 8192; i += 256) {
            int nd = i >> 9, ch = i & 511;
            float v = nf[(size_t)(base + nd) * 512 + ch];
            int pos;
            if (ch < 128) pos = ch;
            else { int j = ch - 128; pos = 128 + (j % 3) * 128 + j / 3; }
            snf[nd * 512 + pos] = v;
        }
        __syncthreads();

        const float* rowA = snf + warp * 512;
        const float* rowB = snf + (warp + 8) * 512;
        const ull* As = (const ull*)rowA;
        const ull* A0 = (const ull*)(rowA + 128);
        const ull* A1 = (const ull*)(rowA + 256);
        const ull* A2 = (const ull*)(rowA + 384);
        const ull* Bs = (const ull*)rowB;
        const ull* B0 = (const ull*)(rowB + 128);
        const ull* B1 = (const ull*)(rowB + 256);
        const ull* B2 = (const ull*)(rowB + 384);

        ull aA[16], aB[16];
        #pragma unroll
        for (int i = 0; i < 16; ++i) { aA[i] = 0; aB[i] = 0; }

        #pragma unroll 4
        for (int u2 = 0; u2 < 64; ++u2) {
            ulonglong2 bsA = *(const ulonglong2*)(sWsP + u2 * 128 + 4 * cg);
            ulonglong2 bsB = *(const ulonglong2*)(sWsP + u2 * 128 + 4 * cg + 2);
            ulonglong2 bvA = *(const ulonglong2*)(sWvP + u2 * 128 + 4 * cg);
            ulonglong2 bvB = *(const ulonglong2*)(sWvP + u2 * 128 + 4 * cg + 2);
            ull xs, x0, x1, x2;
            xs = As[u2]; x0 = A0[u2]; x1 = A1[u2]; x2 = A2[u2];
            fma2(aA[0],  xs, bsA.x); fma2(aA[1],  xs, bsA.y);
            fma2(aA[2],  xs, bsB.x); fma2(aA[3],  xs, bsB.y);
            fma2(aA[4],  x0, bvA.x); fma2(aA[5],  x0, bvA.y);
            fma2(aA[6],  x0, bvB.x); fma2(aA[7],  x0, bvB.y);
            fma2(aA[8],  x1, bvA.x); fma2(aA[9],  x1, bvA.y);
            fma2(aA[10], x1, bvB.x); fma2(aA[11], x1, bvB.y);
            fma2(aA[12], x2, bvA.x); fma2(aA[13], x2, bvA.y);
            fma2(aA[14], x2, bvB.x); fma2(aA[15], x2, bvB.y);
            xs = Bs[u2]; x0 = B0[u2]; x1 = B1[u2]; x2 = B2[u2];
            fma2(aB[0],  xs, bsA.x); fma2(aB[1],  xs, bsA.y);
            fma2(aB[2],  xs, bsB.x); fma2(aB[3],  xs, bsB.y);
            fma2(aB[4],  x0, bvA.x); fma2(aB[5],  x0, bvA.y);
            fma2(aB[6],  x0, bvB.x); fma2(aB[7],  x0, bvB.y);
            fma2(aB[8],  x1, bvA.x); fma2(aB[9],  x1, bvA.y);
            fma2(aB[10], x1, bvB.x); fma2(aB[11], x1, bvB.y);
            fma2(aB[12], x2, bvA.x); fma2(aB[13], x2, bvA.y);
            fma2(aB[14], x2, bvB.x); fma2(aB[15], x2, bvB.y);
        }

        float* oA = g_node + (size_t)(base + warp) * 512;
        float* oB = g_node + (size_t)(base + warp + 8) * 512;
        #pragma unroll
        for (int s = 0; s < 4; ++s) {
            float4 r;
            r.x = rsum(aA[s*4+0]) * inv; r.y = rsum(aA[s*4+1]) * inv;
            r.z = rsum(aA[s*4+2]) * inv; r.w = rsum(aA[s*4+3]) * inv;
            ((float4*)(oA + 128 * s))[cg] = r;
            r.x = rsum(aB[s*4+0]) * inv; r.y = rsum(aB[s*4+1]) * inv;
            r.z = rsum(aB[s*4+2]) * inv; r.w = rsum(aB[s*4+3]) * inv;
            ((float4*)(oB + 128 * s))[cg] = r;
        }
        __syncthreads();
    }
}

// ---------------------------------------------------------------------------
// Kernel 2: edge MLP layers 0..2 -> g_h.  128 edges/CTA, 128 threads. (R3 proven)
// ---------------------------------------------------------------------------
__global__ void __launch_bounds__(128) mlp_kernel(
    const float* __restrict__ ef,
    const float* __restrict__ w0,
    const float* __restrict__ w1,
    const float* __restrict__ w2)
{
    extern __shared__ float sm[];
    float* sw0 = sm;              // 512
    float* sw1 = sw0 + 512;       // 4096
    float* sw2 = sw1 + 4096;      // 4096
    float* sef = sw2 + 4096;      // 1024
    float* hA  = sef + 1024;      // 128*65
    float* hB  = hA + 128 * 65;   // 128*65

    int t = threadIdx.x;
    const float is8 = 0.35355339059327373f; // 1/sqrt(8)
    for (int i = t; i < 512; i += 128) sw0[i] = w0[i] * is8;
    for (int i = t; i < 4096; i += 128) { sw1[i] = w1[i] * 0.125f; sw2[i] = w2[i] * 0.125f; }
    int ebase = blockIdx.x * 128;
    int nvalid = N_EDGES - ebase; if (nvalid > 128) nvalid = 128;
    for (int i = t; i < 1024; i += 128)
        sef[i] = (i < nvalid * 8) ? ef[ebase * 8 + i] : 0.f;
    __syncthreads();

    int es = t & 31;
    int dg = t >> 5;
    float acc[4][16];

    // layer 0
    #pragma unroll
    for (int k = 0; k < 4; ++k)
        #pragma unroll
        for (int d = 0; d < 16; ++d) acc[k][d] = 0.f;
    #pragma unroll
    for (int u = 0; u < 8; ++u) {
        float x0 = sef[(es      ) * 8 + u];
        float x1 = sef[(es + 32) * 8 + u];
        float x2 = sef[(es + 64) * 8 + u];
        float x3 = sef[(es + 96) * 8 + u];
        #pragma unroll
        for (int d = 0; d < 16; ++d) {
            float w = sw0[u * 64 + dg * 16 + d];
            acc[0][d] += x0 * w; acc[1][d] += x1 * w; acc[2][d] += x2 * w; acc[3][d] += x3 * w;
        }
    }
    #pragma unroll
    for (int k = 0; k < 4; ++k)
        #pragma unroll
        for (int d = 0; d < 16; ++d)
            hA[(es + 32 * k) * 65 + dg * 16 + d] = act(acc[k][d]);
    __syncthreads();

    // layer 1
    #pragma unroll
    for (int k = 0; k < 4; ++k)
        #pragma unroll
        for (int d = 0; d < 16; ++d) acc[k][d] = 0.f;
    #pragma unroll 8
    for (int u = 0; u < 64; ++u) {
        float x0 = hA[(es      ) * 65 + u];
        float x1 = hA[(es + 32) * 65 + u];
        float x2 = hA[(es + 64) * 65 + u];
        float x3 = hA[(es + 96) * 65 + u];
        #pragma unroll
        for (int d = 0; d < 16; ++d) {
            float w = sw1[u * 64 + dg * 16 + d];
            acc[0][d] += x0 * w; acc[1][d] += x1 * w; acc[2][d] += x2 * w; acc[3][d] += x3 * w;
        }
    }
    #pragma unroll
    for (int k = 0; k < 4; ++k)
        #pragma unroll
        for (int d = 0; d < 16; ++d)
            hB[(es + 32 * k) * 65 + dg * 16 + d] = act(acc[k][d]);
    __syncthreads();

    // layer 2 -> g_h
    #pragma unroll
    for (int k = 0; k < 4; ++k)
        #pragma unroll
        for (int d = 0; d < 16; ++d) acc[k][d] = 0.f;
    #pragma unroll 8
    for (int u = 0; u < 64; ++u) {
        float x0 = hB[(es      ) * 65 + u];
        float x1 = hB[(es + 32) * 65 + u];
        float x2 = hB[(es + 64) * 65 + u];
        float x3 = hB[(es + 96) * 65 + u];
        #pragma unroll
        for (int d = 0; d < 16; ++d) {
            float w = sw2[u * 64 + dg * 16 + d];
            acc[0][d] += x0 * w; acc[1][d] += x1 * w; acc[2][d] += x2 * w; acc[3][d] += x3 * w;
        }
    }
    #pragma unroll
    for (int k = 0; k < 4; ++k) {
        int e = ebase + es + 32 * k;
        if (e < N_EDGES) {
            #pragma unroll
            for (int d = 0; d < 16; ++d)
                g_h[(size_t)e * 64 + dg * 16 + d] = act(acc[k][d]);
        }
    }
}

// ---------------------------------------------------------------------------
// Kernel 3: fused tpw + tensor product + output GEMMs. (R8 measured best)
// 32 edges/CTA, 256 threads (warp w owns edges 4w..4w+3; lane cg owns cols 4cg..+3)
// out_v factorization: out_v[e,n,i] = sh1_i * (P@Wv_top)[e,n] + ((Q*vs_i)@Wv_bot)[e,n]
// ssv uses the SoA node layout [s|v0|v1|v2] to match g_node.
// ---------------------------------------------------------------------------
__global__ void __launch_bounds__(256) edge_kernel(
    const float* __restrict__ ea,     // edge_attrs (E,4)
    const int*   __restrict__ eidx,   // edge_index (2,E): sender first
    const float* __restrict__ w3,     // (64,512)
    const float* __restrict__ Wos,    // (256,128)
    const float* __restrict__ Wov,    // (256,128)
    float* __restrict__ out)
{
    extern __shared__ float sm[];
    float* ssv = sm;                  // 32*512 = 16384 (gathered, SoA)
    float* sA  = ssv + 16384;         // 32*256 = 8192 (mid_s, coef folded)
    float* sP  = sA + 8192;           // 32*128 = 4096
    float* sQ  = sP + 4096;           // 32*128 = 4096
    float* sh  = sQ + 4096;           // 32*64  = 2048
    float* sW  = sh + 2048;           // 64*128 = 8192 (B staging)
    float* sea = sW + 8192;           // 128
    int*   snd = (int*)(sea + 128);   // 32

    const float C0 = 0.70710678118654752f / 128.0f;                       // sqrt(.5)/(8*16)
    const float C3 = 0.70710678118654752f / (128.0f * 1.7320508075688772f);

    int t = threadIdx.x;
    int warp = t >> 5;
    int cg = t & 31;
    int ebase = blockIdx.x * 32;

    if (t < 32) snd[t] = eidx[ebase + t];
    if (t >= 128 && t < 256) sea[t - 128] = ea[ebase * 4 + (t - 128)];
    __syncthreads();

    { // gather node rows (32 x 512 floats, 8 threads/row, float4)
        int r = t >> 3, q = t & 7;
        const float4* src = (const float4*)g_node + (size_t)snd[r] * 128;
        float4* dst = (float4*)ssv + r * 128;
        #pragma unroll
        for (int j = 0; j < 16; ++j) dst[q + 8 * j] = src[q + 8 * j];
    }
    { // h tile (512 float4)
        const float4* src = (const float4*)g_h + (size_t)ebase * 16;
        float4* dst = (float4*)sh;
        dst[t] = src[t];
        dst[t + 256] = src[t + 256];
    }
    __syncthreads();

    int e0 = warp * 4;
    const float4* w34 = (const float4*)w3;
    float4* sW4 = (float4*)sW;

    // ---- tpw chunks -> A / P / Q (coefficients folded) ----
    for (int c = 0; c < 4; ++c) {
        #pragma unroll
        for (int j = 0; j < 8; ++j) {
            int idx = t + 256 * j;           // < 2048
            int u = idx >> 5, q = idx & 31;
            sW4[idx] = w34[u * 128 + c * 32 + q];
        }
        __syncthreads();

        float acc[4][4];
        #pragma unroll
        for (int k = 0; k < 4; ++k) { acc[k][0]=0.f; acc[k][1]=0.f; acc[k][2]=0.f; acc[k][3]=0.f; }
        #pragma unroll 4
        for (int u = 0; u < 64; ++u) {
            float4 b = sW4[u * 32 + cg];
            #pragma unroll
            for (int k = 0; k < 4; ++k) {
                float a = sh[(e0 + k) * 64 + u];
                acc[k][0] += a * b.x; acc[k][1] += a * b.y;
                acc[k][2] += a * b.z; acc[k][3] += a * b.w;
            }
        }
        #pragma unroll
        for (int k = 0; k < 4; ++k) {
            int e = e0 + k;
            float s0 = sea[e * 4];
            if (c == 0) {
                float4 sv = ((const float4*)(ssv + e * 512))[cg];
                float4 v;
                v.x = C0 * acc[k][0] * sv.x * s0; v.y = C0 * acc[k][1] * sv.y * s0;
                v.z = C0 * acc[k][2] * sv.z * s0; v.w = C0 * acc[k][3] * sv.w * s0;
                ((float4*)sA)[e * 64 + cg] = v;
            } else if (c == 1) {
                float4 sv = ((const float4*)(ssv + e * 512))[cg];
                float4 v;
                v.x = C0 * acc[k][0] * sv.x; v.y = C0 * acc[k][1] * sv.y;
                v.z = C0 * acc[k][2] * sv.z; v.w = C0 * acc[k][3] * sv.w;
                ((float4*)sP)[e * 32 + cg] = v;
            } else if (c == 2) {
                float4 v;
                v.x = C0 * acc[k][0] * s0; v.y = C0 * acc[k][1] * s0;
                v.z = C0 * acc[k][2] * s0; v.w = C0 * acc[k][3] * s0;
                ((float4*)sQ)[e * 32 + cg] = v;
            } else {
                float s1 = sea[e * 4 + 1], s2 = sea[e * 4 + 2], s3 = sea[e * 4 + 3];
                float4 v0 = ((const float4*)(ssv + e * 512 + 128))[cg];
                float4 v1 = ((const float4*)(ssv + e * 512 + 256))[cg];
                float4 v2 = ((const float4*)(ssv + e * 512 + 384))[cg];
                float4 v;
                v.x = C3 * acc[k][0] * (v0.x * s1 + v1.x * s2 + v2.x * s3);
                v.y = C3 * acc[k][1] * (v0.y * s1 + v1.y * s2 + v2.y * s3);
                v.z = C3 * acc[k][2] * (v0.z * s1 + v1.z * s2 + v2.z * s3);
                v.w = C3 * acc[k][3] * (v0.w * s1 + v1.w * s2 + v2.w * s3);
                ((float4*)sA)[e * 64 + 32 + cg] = v;
            }
        }
        __syncthreads();
    }

    // ---- out_s = A(32x256) @ Wos(256x128) ----
    {
        float accs[4][4];
        #pragma unroll
        for (int k = 0; k < 4; ++k) { accs[k][0]=0.f; accs[k][1]=0.f; accs[k][2]=0.f; accs[k][3]=0.f; }
        const float4* Ws4 = (const float4*)Wos;
        for (int kt = 0; kt < 4; ++kt) {
            #pragma unroll
            for (int j = 0; j < 8; ++j) { int idx = t + 256 * j; sW4[idx] = Ws4[kt * 2048 + idx]; }
            __syncthreads();
            #pragma unroll 4
            for (int u = 0; u < 64; ++u) {
                float4 b = sW4[u * 32 + cg];
                #pragma unroll
                for (int k = 0; k < 4; ++k) {
                    float a = sA[(e0 + k) * 256 + kt * 64 + u];
                    accs[k][0] += a * b.x; accs[k][1] += a * b.y;
                    accs[k][2] += a * b.z; accs[k][3] += a * b.w;
                }
            }
            __syncthreads();
        }
        #pragma unroll
        for (int k = 0; k < 4; ++k) {
            size_t e = (size_t)(ebase + e0 + k);
            ((float4*)out)[e * 128 + cg] =
                make_float4(accs[k][0], accs[k][1], accs[k][2], accs[k][3]);
        }
    }

    // ---- PV = P(32x128) @ Wv_top(128x128) ----
    float accp[4][4];
    #pragma unroll
    for (int k = 0; k < 4; ++k) { accp[k][0]=0.f; accp[k][1]=0.f; accp[k][2]=0.f; accp[k][3]=0.f; }
    const float4* Wv4 = (const float4*)Wov;
    for (int kt = 0; kt < 2; ++kt) {
        #pragma unroll
        for (int j = 0; j < 8; ++j) { int idx = t + 256 * j; sW4[idx] = Wv4[kt * 2048 + idx]; }
        __syncthreads();
        #pragma unroll 4
        for (int u = 0; u < 64; ++u) {
            float4 b = sW4[u * 32 + cg];
            #pragma unroll
            for (int k = 0; k < 4; ++k) {
                float a = sP[(e0 + k) * 128 + kt * 64 + u];
                accp[k][0] += a * b.x; accp[k][1] += a * b.y;
                accp[k][2] += a * b.z; accp[k][3] += a * b.w;
            }
        }
        __syncthreads();
    }

    // ---- QV_i = (Q*vs_i) @ Wv_bot (SoA v reads) ----
    float accq[3][4][4];
    #pragma unroll
    for (int i = 0; i < 3; ++i)
        #pragma unroll
        for (int k = 0; k < 4; ++k) { accq[i][k][0]=0.f; accq[i][k][1]=0.f; accq[i][k][2]=0.f; accq[i][k][3]=0.f; }
    for (int kt = 0; kt < 2; ++kt) {
        #pragma unroll
        for (int j = 0; j < 8; ++j) { int idx = t + 256 * j; sW4[idx] = Wv4[(128 + kt * 64) * 32 + idx]; }
        __syncthreads();
        #pragma unroll 2
        for (int u = 0; u < 64; ++u) {
            float4 b = sW4[u * 32 + cg];
            int uu = kt * 64 + u;
            #pragma unroll
            for (int k = 0; k < 4; ++k) {
                int e = e0 + k;
                float q = sQ[e * 128 + uu];
                float q0 = q * ssv[e * 512 + 128 + uu];
                float q1 = q * ssv[e * 512 + 256 + uu];
                float q2 = q * ssv[e * 512 + 384 + uu];
                accq[0][k][0] += q0 * b.x; accq[0][k][1] += q0 * b.y; accq[0][k][2] += q0 * b.z; accq[0][k][3] += q0 * b.w;
                accq[1][k][0] += q1 * b.x; accq[1][k][1] += q1 * b.y; accq[1][k][2] += q1 * b.z; accq[1][k][3] += q1 * b.w;
                accq[2][k][0] += q2 * b.x; accq[2][k][1] += q2 * b.y; accq[2][k][2] += q2 * b.z; accq[2][k][3] += q2 * b.w;
            }
        }
        __syncthreads();
    }

    // ---- combine + restage out_v through smem for coalesced stores ----
    float* vbuf = sA;   // sA(8192)+sP(4096) contiguous = 12288 floats = 32*384
    #pragma unroll
    for (int k = 0; k < 4; ++k) {
        int e = e0 + k;
        float s1 = sea[e * 4 + 1], s2 = sea[e * 4 + 2], s3 = sea[e * 4 + 3];
        #pragma unroll
        for (int j = 0; j < 4; ++j) {
            int n = cg * 4 + j;
            float pvv = accp[k][j];
            vbuf[e * 384 + n * 3 + 0] = s1 * pvv + accq[0][k][j];
            vbuf[e * 384 + n * 3 + 1] = s2 * pvv + accq[1][k][j];
            vbuf[e * 384 + n * 3 + 2] = s3 * pvv + accq[2][k][j];
        }
    }
    __syncthreads();
    float4* vb4 = (float4*)vbuf;
    #pragma unroll
    for (int j = 0; j < 12; ++j) {
        int idx = t + 256 * j;      // < 3072
        int e = idx / 96, rem = idx % 96;
        ((float4*)out)[(size_t)(ebase + e) * 128 + 32 + rem] = vb4[idx];
    }
}

// ---------------------------------------------------------------------------
extern "C" void kernel_launch(void* const* d_in, const int* in_sizes, int n_in,
                              void* d_out, int out_size) {
    const float* node_feats = (const float*)d_in[0];
    const float* edge_attrs = (const float*)d_in[1];
    const float* edge_feats = (const float*)d_in[2];
    const int*   edge_index = (const int*)d_in[3];
    const float* W_up_s  = (const float*)d_in[4];
    const float* W_up_v  = (const float*)d_in[5];
    const float* mlp_w0  = (const float*)d_in[6];
    const float* mlp_w1  = (const float*)d_in[7];
    const float* mlp_w2  = (const float*)d_in[8];
    const float* mlp_w3  = (const float*)d_in[9];
    const float* W_out_s = (const float*)d_in[10];
    const float* W_out_v = (const float*)d_in[11];
    float* out = (float*)d_out;

    size_t smem1 = (size_t)40960 * 4;   // 160 KB
    size_t smem2 = (size_t)26368 * 4;   // 103 KB
    size_t smem3 = (size_t)43200 * 4;   // 168.75 KB
    cudaFuncSetAttribute(node_kernel, cudaFuncAttributeMaxDynamicSharedMemorySize, (int)smem1);
    cudaFuncSetAttribute(mlp_kernel,  cudaFuncAttributeMaxDynamicSharedMemorySize, (int)smem2);
    cudaFuncSetAttribute(edge_kernel, cudaFuncAttributeMaxDynamicSharedMemorySize, (int)smem3);

    node_kernel<<<148, 256, smem1>>>(node_feats, W_up_s, W_up_v);
    mlp_kernel<<<(N_EDGES + 127) / 128, 128, smem2>>>(edge_feats, mlp_w0, mlp_w1, mlp_w2);
    edge_kernel<<<N_EDGES / 32, 256, smem3>>>(edge_attrs, edge_index, mlp_w3,
                                              W_out_s, W_out_v, out);
}